// round 10
// baseline (speedup 1.0000x reference)
#include <cuda_runtime.h>
#include <math.h>

// SmoothTopKGate: s (nrows, 8) fp32 -> sigmoid((s - theta)/tau).
// n* = first i with mean_rows(f(theta_i)) < TOL (global stop), all rows then
// apply exactly n* Newton updates from theta0 = 3rd largest.
//
// pass1: CAP1=6 iterations, 2 rows/thread, ex2+pairwise-rcp sigmoid
//        (12 rt8-MUFU/row-iter; tanh.approx measured half-rate -> reverted),
//        exact fixed-point per-iteration f-sums, theta planes, last-block pick.
// cont:  resumes from plane[CAP1-1] for iters 6..23 if no crossing (cold).
// fb:    exact full-depth recompute for n*>=24 (cold).
// pass2: reads theta_{n*} plane, emits 8 gates (DRAM-bound ~40us).

constexpr int    S_DIM      = 8;
constexpr float  KSEL       = 2.0f;
constexpr float  INV_TAU    = 100.0f;
constexpr int    MAX_ITER   = 100;
constexpr int    CAP1       = 6;              // pass1 iterations (n* ~ 5)
constexpr int    CAP2       = 24;             // pass1+cont total planes
constexpr double TOL        = 1e-3;
constexpr float  FP_SCALE   = 4194304.0f;     // 2^22 fixed point
constexpr double FP_SCALE_D = 4194304.0;
constexpr int    NW         = 8;              // warps per 256-thread block
constexpr int    PLANE_ROWS = 4194304;
constexpr float  CEXP       = 144.26950408889634f;   // 100 * log2(e)

__device__ long long g_sums[CAP2];
__device__ long long g_sums_fb[MAX_ITER];
__device__ long long g_tail_fb[MAX_ITER];
__device__ int       g_nstar;
__device__ unsigned  g_done1, g_done_c, g_done_fb;
__device__ float     g_theta[(size_t)CAP2 * PLANE_ROWS];  // theta after (i+1) updates

// ---------------- helpers ----------------
__device__ __forceinline__ float ex2_approx(float x) {
    float y; asm("ex2.approx.f32 %0, %1;" : "=f"(y) : "f"(x)); return y;
}
__device__ __forceinline__ float rcp_approx(float x) {
    float y; asm("rcp.approx.f32 %0, %1;" : "=f"(y) : "f"(x)); return y;
}

__device__ __forceinline__ float sigmoid_f(float x) {       // exact output path
    return __fdividef(1.0f, 1.0f + __expf(-x));
}

// exact (R4) evaluation — deep fallback + pass2 replay
__device__ __forceinline__ void eval_fg(const float t[S_DIM], float theta,
                                        float& f, float& g) {
    float fs = 0.0f, gs = 0.0f;
#pragma unroll
    for (int j = 0; j < S_DIM; ++j) {
        float x = (t[j] - theta) * INV_TAU;
        float m = sigmoid_f(x);
        fs += m;
        gs += m * (1.0f - m);
    }
    f = fs - KSEL;
    g = gs;
}

// fast evaluation: hoisted exp args (b_j = t_j*CEXP) + pairwise reciprocals.
// e clamped to 1e15 so p*q never overflows for mixed pairs -> no inf*0 NaN.
__device__ __forceinline__ void eval_fg_fast(const float b[S_DIM], float theta,
                                             float& f, float& g) {
    float h = theta * CEXP;
    float e[S_DIM];
#pragma unroll
    for (int j = 0; j < S_DIM; ++j)
        e[j] = fminf(ex2_approx(h - b[j]), 1e15f);   // exp(-(t_j-theta)*100)
    float fs = 0.0f, gs = 0.0f;
#pragma unroll
    for (int j = 0; j < S_DIM; j += 2) {
        float p = 1.0f + e[j];
        float q = 1.0f + e[j + 1];
        float r = rcp_approx(p * q);
        float m0 = q * r;
        float m1 = p * r;
        fs += m0; fs += m1;
        gs = fmaf(m0, m0, gs);
        gs = fmaf(m1, m1, gs);
    }
    f = fs - KSEL;
    g = fs - gs;          // sum m(1-m) = sum m - sum m^2
}

__device__ __forceinline__ float third_largest(const float t[S_DIM]) {
    float a1 = fmaxf(t[0], t[1]);
    float a2 = fminf(t[0], t[1]);
    float a3 = __int_as_float(0xff800000);  // -inf
#pragma unroll
    for (int j = 2; j < S_DIM; ++j) {
        float v  = t[j];
        float m1 = fmaxf(a1, v);
        float r1 = fminf(a1, v);
        float m2 = fmaxf(a2, r1);
        float r2 = fminf(a2, r1);
        float m3 = fmaxf(a3, r2);
        a1 = m1; a2 = m2; a3 = m3;
    }
    return a3;   // (k+1)-th largest for k=2
}

__device__ __forceinline__ void load_row(const float* __restrict__ s, int row,
                                         float t[S_DIM]) {
    const float4* p = reinterpret_cast<const float4*>(s + (size_t)row * S_DIM);
    float4 v0 = p[0];
    float4 v1 = p[1];
    t[0] = v0.x; t[1] = v0.y; t[2] = v0.z; t[3] = v0.w;
    t[4] = v1.x; t[5] = v1.y; t[6] = v1.z; t[7] = v1.w;
}

__global__ void k_zero() {
    for (int i = threadIdx.x; i < MAX_ITER; i += blockDim.x) {
        g_sums_fb[i] = 0;
        g_tail_fb[i] = 0;
        if (i < CAP2) g_sums[i] = 0;
    }
    if (threadIdx.x == 0) {
        g_nstar = -2;
        g_done1 = 0u; g_done_c = 0u; g_done_fb = 0u;
    }
}

// ---------------- pass 1: iterations 0..CAP1-1, 2 rows/thread ----------------
__global__ void __launch_bounds__(256) k_pass1(const float* __restrict__ s, int nrows) {
    __shared__ int ss[NW][CAP1];
    const int tid  = threadIdx.x;
    const int wid  = tid >> 5;
    const int lane = tid & 31;

    if (tid < NW * CAP1) (&ss[0][0])[tid] = 0;
    __syncthreads();

    const int T    = gridDim.x * blockDim.x;
    const int rowA = blockIdx.x * blockDim.x + tid;
    const int rowB = rowA + T;
    const bool va = rowA < nrows;
    const bool vb = rowB < nrows;
    const bool planes = (nrows <= PLANE_ROWS);

    float bA[S_DIM], bB[S_DIM];
    float thA = 0.0f, thB = 0.0f;
    {
        float t[S_DIM];
        if (va) {
            load_row(s, rowA, t);
            thA = third_largest(t);
#pragma unroll
            for (int j = 0; j < S_DIM; ++j) bA[j] = t[j] * CEXP;
        } else {
#pragma unroll
            for (int j = 0; j < S_DIM; ++j) bA[j] = 0.0f;
        }
        if (vb) {
            load_row(s, rowB, t);
            thB = third_largest(t);
#pragma unroll
            for (int j = 0; j < S_DIM; ++j) bB[j] = t[j] * CEXP;
        } else {
#pragma unroll
            for (int j = 0; j < S_DIM; ++j) bB[j] = 0.0f;
        }
    }

#pragma unroll 1
    for (int i = 0; i < CAP1; ++i) {
        float fA, gA, fB, gB;
        eval_fg_fast(bA, thA, fA, gA);
        eval_fg_fast(bB, thB, fB, gB);

        int fx = (va ? __float2int_rn(fA * FP_SCALE) : 0)
               + (vb ? __float2int_rn(fB * FP_SCALE) : 0);
        int wsum = __reduce_add_sync(0xffffffffu, fx);
        if (lane == 0) ss[wid][i] = wsum;

        if (va & (gA > 0.0f))
            thA = fmaf(fA * 0.01f, rcp_approx(gA), thA);   // theta + f/(100 g)
        if (vb & (gB > 0.0f))
            thB = fmaf(fB * 0.01f, rcp_approx(gB), thB);

        if (planes) {
            if (va) g_theta[(size_t)i * PLANE_ROWS + rowA] = thA;
            if (vb) g_theta[(size_t)i * PLANE_ROWS + rowB] = thB;
        }
    }

    __syncthreads();
    for (int idx = tid; idx < CAP1; idx += blockDim.x) {
        long long tot = 0;
#pragma unroll
        for (int w = 0; w < NW; ++w) tot += (long long)ss[w][idx];
        if (tot)
            atomicAdd(reinterpret_cast<unsigned long long*>(&g_sums[idx]),
                      (unsigned long long)tot);
    }

    __threadfence();
    __shared__ bool is_last;
    if (tid == 0)
        is_last = (atomicAdd(&g_done1, 1u) == (unsigned)(gridDim.x - 1));
    __syncthreads();
    if (is_last && tid == 0) {
        double denom = (double)nrows * FP_SCALE_D;
        int n = -1;   // -1 => continuation / fallback required
        for (int i = 0; i < CAP1; ++i) {
            double mean = (double)g_sums[i] / denom;
            if (mean < TOL) { n = i; break; }
        }
        g_nstar = n;
        __threadfence();
    }
}

// ---------------- continuation: iterations CAP1..CAP2-1 (cold) ----------------
__global__ void __launch_bounds__(256) k_cont(const float* __restrict__ s, int nrows) {
    if (g_nstar != -1) return;
    if (nrows > PLANE_ROWS) return;

    __shared__ int ss[NW][CAP2 - CAP1];
    const int tid  = threadIdx.x;
    const int wid  = tid >> 5;
    const int lane = tid & 31;

    if (tid < NW * (CAP2 - CAP1)) (&ss[0][0])[tid] = 0;
    __syncthreads();

    int row = blockIdx.x * blockDim.x + tid;
    bool valid = row < nrows;

    float t[S_DIM], b[S_DIM];
    float theta = 0.0f;
    if (valid) {
        load_row(s, row, t);
        theta = g_theta[(size_t)(CAP1 - 1) * PLANE_ROWS + row];  // exact resume
    } else {
#pragma unroll
        for (int j = 0; j < S_DIM; ++j) t[j] = 0.0f;
    }
#pragma unroll
    for (int j = 0; j < S_DIM; ++j) b[j] = t[j] * CEXP;

#pragma unroll 1
    for (int i = CAP1; i < CAP2; ++i) {
        float f, g;
        eval_fg_fast(b, theta, f, g);
        int fx = valid ? __float2int_rn(f * FP_SCALE) : 0;
        int wsum = __reduce_add_sync(0xffffffffu, fx);
        if (lane == 0) ss[wid][i - CAP1] = wsum;

        if (valid) {
            float thn = theta - __fdividef(f, -100.0f * g);
            if ((g > 0.0f) && (thn != theta)) theta = thn;
        }
        if (valid)
            g_theta[(size_t)i * PLANE_ROWS + row] = theta;
    }

    __syncthreads();
    for (int idx = tid; idx < CAP2 - CAP1; idx += blockDim.x) {
        long long tot = 0;
#pragma unroll
        for (int w = 0; w < NW; ++w) tot += (long long)ss[w][idx];
        if (tot)
            atomicAdd(reinterpret_cast<unsigned long long*>(&g_sums[CAP1 + idx]),
                      (unsigned long long)tot);
    }

    __threadfence();
    __shared__ bool is_last;
    if (tid == 0)
        is_last = (atomicAdd(&g_done_c, 1u) == (unsigned)(gridDim.x - 1));
    __syncthreads();
    if (is_last && tid == 0) {
        double denom = (double)nrows * FP_SCALE_D;
        int n = -1;
        for (int i = CAP1; i < CAP2; ++i) {
            double mean = (double)g_sums[i] / denom;
            if (mean < TOL) { n = i; break; }
        }
        g_nstar = n;    // stays -1 -> deep fallback
        __threadfence();
    }
}

// ---------------- deep fallback: exact full depth (cold) ----------------
__global__ void __launch_bounds__(256) k_fb_pass1(const float* __restrict__ s, int nrows) {
    if (g_nstar >= 0) return;

    __shared__ long long ss[NW][MAX_ITER];
    const int tid  = threadIdx.x;
    const int wid  = tid >> 5;
    const int lane = tid & 31;

    for (int i = tid; i < NW * MAX_ITER; i += blockDim.x)
        (&ss[0][0])[i] = 0;
    __syncthreads();

    const int stride = gridDim.x * blockDim.x;
    for (int row = blockIdx.x * blockDim.x + tid; ; row += stride) {
        bool valid = row < nrows;
        if (!__any_sync(0xffffffffu, valid)) break;

        float t[S_DIM];
        float theta = 0.0f;
        if (valid) {
            load_row(s, row, t);
            theta = third_largest(t);
        } else {
#pragma unroll
            for (int j = 0; j < S_DIM; ++j) t[j] = 0.0f;
        }

        bool frozen = !valid;
        int  i = 0;
        int  wsum = 0;

#pragma unroll 1
        for (; i < MAX_ITER; ++i) {
            float f, g;
            eval_fg(t, theta, f, g);
            int fx = valid ? __float2int_rn(f * FP_SCALE) : 0;
            wsum = __reduce_add_sync(0xffffffffu, fx);
            if (lane == 0) ss[wid][i] += (long long)wsum;

            if (!frozen) {
                float thn = theta - __fdividef(f, -100.0f * g);
                if ((g > 0.0f) && (thn != theta)) theta = thn;
                else frozen = true;
            }
            if (__all_sync(0xffffffffu, frozen)) { ++i; break; }
        }

        if (lane == 0 && i < MAX_ITER && wsum != 0)
            atomicAdd(reinterpret_cast<unsigned long long*>(&g_tail_fb[i]),
                      (unsigned long long)(long long)wsum);
    }

    __syncthreads();
    for (int idx = tid; idx < MAX_ITER; idx += blockDim.x) {
        long long tot = 0;
#pragma unroll
        for (int w = 0; w < NW; ++w) tot += ss[w][idx];
        if (tot)
            atomicAdd(reinterpret_cast<unsigned long long*>(&g_sums_fb[idx]),
                      (unsigned long long)tot);
    }

    __threadfence();
    __shared__ bool is_last;
    if (tid == 0)
        is_last = (atomicAdd(&g_done_fb, 1u) == (unsigned)(gridDim.x - 1));
    __syncthreads();
    if (is_last && tid == 0) {
        double denom = (double)nrows * FP_SCALE_D;
        long long carry = 0;
        int n = MAX_ITER;
        for (int i = 0; i < MAX_ITER; ++i) {
            carry += g_tail_fb[i];
            double mean = (double)(g_sums_fb[i] + carry) / denom;
            if (mean < TOL) { n = i; break; }
        }
        g_nstar = n;
        __threadfence();
    }
}

// ---------------- pass 2 ----------------
__global__ void __launch_bounds__(256) k_pass2(const float* __restrict__ s,
                                               float* __restrict__ out, int nrows) {
    int row = blockIdx.x * blockDim.x + threadIdx.x;
    if (row >= nrows) return;

    float t[S_DIM];
    load_row(s, row, t);

    int n = g_nstar;   // uniform across grid
    float theta;
    if (n > 0 && n <= CAP2 && nrows <= PLANE_ROWS) {
        theta = g_theta[(size_t)(n - 1) * PLANE_ROWS + row];   // theta after n updates
    } else if (n == 0) {
        theta = third_largest(t);
    } else {
        theta = third_largest(t);
#pragma unroll 1
        for (int i = 0; i < n; ++i) {
            float f, g;
            eval_fg(t, theta, f, g);
            float thn = theta - __fdividef(f, -100.0f * g);
            if ((g > 0.0f) && (thn != theta)) theta = thn;
            else break;
        }
    }

    float4 o0, o1;
    o0.x = sigmoid_f((t[0] - theta) * INV_TAU);
    o0.y = sigmoid_f((t[1] - theta) * INV_TAU);
    o0.z = sigmoid_f((t[2] - theta) * INV_TAU);
    o0.w = sigmoid_f((t[3] - theta) * INV_TAU);
    o1.x = sigmoid_f((t[4] - theta) * INV_TAU);
    o1.y = sigmoid_f((t[5] - theta) * INV_TAU);
    o1.z = sigmoid_f((t[6] - theta) * INV_TAU);
    o1.w = sigmoid_f((t[7] - theta) * INV_TAU);

    float4* po = reinterpret_cast<float4*>(out + (size_t)row * S_DIM);
    po[0] = o0;
    po[1] = o1;
}

extern "C" void kernel_launch(void* const* d_in, const int* in_sizes, int n_in,
                              void* d_out, int out_size) {
    const float* s = (const float*)d_in[0];
    float* out = (float*)d_out;
    int nrows = in_sizes[0] / S_DIM;

    k_zero<<<1, 128>>>();

    const int threads = 256;
    int blocks  = (nrows + threads - 1) / threads;
    int blocks2 = (nrows + 2 * threads - 1) / (2 * threads);   // 2 rows/thread
    k_pass1<<<blocks2, threads>>>(s, nrows);
    k_cont<<<blocks, threads>>>(s, nrows);      // cold unless n* >= CAP1
    k_fb_pass1<<<592, threads>>>(s, nrows);     // cold unless n* >= CAP2
    k_pass2<<<blocks, threads>>>(s, out, nrows);
}

// round 11
// speedup vs baseline: 4.0047x; 4.0047x over previous
#include <cuda_runtime.h>
#include <math.h>

// SmoothTopKGate: s (nrows, 8) fp32 -> sigmoid((s - theta)/tau).
// n* = first i with mean_rows(f(theta_i)) < TOL (global stop), all rows then
// apply exactly n* Newton updates from theta0 = 3rd largest.
//
// Measured: n* = 6 (bracketed by CAP1=7 hit / CAP1=6 miss).
// pass1: CAP1=7 iterations, 2 rows/thread, ex2+pairwise-rcp sigmoid,
//        exact fixed-point per-iteration f-sums, theta planes, last-block pick.
// cont:  resumes from plane[CAP1-1] for iters 7..14 if no crossing (cold).
// fb:    exact full-depth recompute for n*>=15 (cold).
// pass2: reads theta_{n*} plane, emits 8 gates (DRAM-bound ~40us).

constexpr int    S_DIM      = 8;
constexpr float  KSEL       = 2.0f;
constexpr float  INV_TAU    = 100.0f;
constexpr int    MAX_ITER   = 100;
constexpr int    CAP1       = 7;              // pass1 iterations (n* = 6 measured)
constexpr int    CAP2       = 15;             // pass1+cont total planes
constexpr double TOL        = 1e-3;
constexpr float  FP_SCALE   = 4194304.0f;     // 2^22 fixed point
constexpr double FP_SCALE_D = 4194304.0;
constexpr int    NW         = 8;              // warps per 256-thread block
constexpr int    PLANE_ROWS = 4194304;
constexpr float  CEXP       = 144.26950408889634f;   // 100 * log2(e)

__device__ long long g_sums[CAP2];
__device__ long long g_sums_fb[MAX_ITER];
__device__ long long g_tail_fb[MAX_ITER];
__device__ int       g_nstar;
__device__ unsigned  g_done1, g_done_c, g_done_fb;
__device__ float     g_theta[(size_t)CAP2 * PLANE_ROWS];  // theta after (i+1) updates

// ---------------- helpers ----------------
__device__ __forceinline__ float ex2_approx(float x) {
    float y; asm("ex2.approx.f32 %0, %1;" : "=f"(y) : "f"(x)); return y;
}
__device__ __forceinline__ float rcp_approx(float x) {
    float y; asm("rcp.approx.f32 %0, %1;" : "=f"(y) : "f"(x)); return y;
}

__device__ __forceinline__ float sigmoid_f(float x) {       // exact output path
    return __fdividef(1.0f, 1.0f + __expf(-x));
}

// exact (R4) evaluation — deep fallback + pass2 replay
__device__ __forceinline__ void eval_fg(const float t[S_DIM], float theta,
                                        float& f, float& g) {
    float fs = 0.0f, gs = 0.0f;
#pragma unroll
    for (int j = 0; j < S_DIM; ++j) {
        float x = (t[j] - theta) * INV_TAU;
        float m = sigmoid_f(x);
        fs += m;
        gs += m * (1.0f - m);
    }
    f = fs - KSEL;
    g = gs;
}

// fast evaluation: hoisted exp args (b_j = t_j*CEXP) + pairwise reciprocals.
// e clamped to 1e15 so p*q never overflows for mixed pairs -> no inf*0 NaN.
__device__ __forceinline__ void eval_fg_fast(const float b[S_DIM], float theta,
                                             float& f, float& g) {
    float h = theta * CEXP;
    float e[S_DIM];
#pragma unroll
    for (int j = 0; j < S_DIM; ++j)
        e[j] = fminf(ex2_approx(h - b[j]), 1e15f);   // exp(-(t_j-theta)*100)
    float fs = 0.0f, gs = 0.0f;
#pragma unroll
    for (int j = 0; j < S_DIM; j += 2) {
        float p = 1.0f + e[j];
        float q = 1.0f + e[j + 1];
        float r = rcp_approx(p * q);
        float m0 = q * r;
        float m1 = p * r;
        fs += m0; fs += m1;
        gs = fmaf(m0, m0, gs);
        gs = fmaf(m1, m1, gs);
    }
    f = fs - KSEL;
    g = fs - gs;          // sum m(1-m) = sum m - sum m^2
}

__device__ __forceinline__ float third_largest(const float t[S_DIM]) {
    float a1 = fmaxf(t[0], t[1]);
    float a2 = fminf(t[0], t[1]);
    float a3 = __int_as_float(0xff800000);  // -inf
#pragma unroll
    for (int j = 2; j < S_DIM; ++j) {
        float v  = t[j];
        float m1 = fmaxf(a1, v);
        float r1 = fminf(a1, v);
        float m2 = fmaxf(a2, r1);
        float r2 = fminf(a2, r1);
        float m3 = fmaxf(a3, r2);
        a1 = m1; a2 = m2; a3 = m3;
    }
    return a3;   // (k+1)-th largest for k=2
}

__device__ __forceinline__ void load_row(const float* __restrict__ s, int row,
                                         float t[S_DIM]) {
    const float4* p = reinterpret_cast<const float4*>(s + (size_t)row * S_DIM);
    float4 v0 = p[0];
    float4 v1 = p[1];
    t[0] = v0.x; t[1] = v0.y; t[2] = v0.z; t[3] = v0.w;
    t[4] = v1.x; t[5] = v1.y; t[6] = v1.z; t[7] = v1.w;
}

__global__ void k_zero() {
    for (int i = threadIdx.x; i < MAX_ITER; i += blockDim.x) {
        g_sums_fb[i] = 0;
        g_tail_fb[i] = 0;
        if (i < CAP2) g_sums[i] = 0;
    }
    if (threadIdx.x == 0) {
        g_nstar = -2;
        g_done1 = 0u; g_done_c = 0u; g_done_fb = 0u;
    }
}

// ---------------- pass 1: iterations 0..CAP1-1, 2 rows/thread ----------------
__global__ void __launch_bounds__(256) k_pass1(const float* __restrict__ s, int nrows) {
    __shared__ int ss[NW][CAP1];
    const int tid  = threadIdx.x;
    const int wid  = tid >> 5;
    const int lane = tid & 31;

    if (tid < NW * CAP1) (&ss[0][0])[tid] = 0;
    __syncthreads();

    const int T    = gridDim.x * blockDim.x;
    const int rowA = blockIdx.x * blockDim.x + tid;
    const int rowB = rowA + T;
    const bool va = rowA < nrows;
    const bool vb = rowB < nrows;
    const bool planes = (nrows <= PLANE_ROWS);

    float bA[S_DIM], bB[S_DIM];
    float thA = 0.0f, thB = 0.0f;
    {
        float t[S_DIM];
        if (va) {
            load_row(s, rowA, t);
            thA = third_largest(t);
#pragma unroll
            for (int j = 0; j < S_DIM; ++j) bA[j] = t[j] * CEXP;
        } else {
#pragma unroll
            for (int j = 0; j < S_DIM; ++j) bA[j] = 0.0f;
        }
        if (vb) {
            load_row(s, rowB, t);
            thB = third_largest(t);
#pragma unroll
            for (int j = 0; j < S_DIM; ++j) bB[j] = t[j] * CEXP;
        } else {
#pragma unroll
            for (int j = 0; j < S_DIM; ++j) bB[j] = 0.0f;
        }
    }

#pragma unroll 1
    for (int i = 0; i < CAP1; ++i) {
        float fA, gA, fB, gB;
        eval_fg_fast(bA, thA, fA, gA);
        eval_fg_fast(bB, thB, fB, gB);

        int fx = (va ? __float2int_rn(fA * FP_SCALE) : 0)
               + (vb ? __float2int_rn(fB * FP_SCALE) : 0);
        int wsum = __reduce_add_sync(0xffffffffu, fx);
        if (lane == 0) ss[wid][i] = wsum;

        if (va & (gA > 0.0f))
            thA = fmaf(fA * 0.01f, rcp_approx(gA), thA);   // theta + f/(100 g)
        if (vb & (gB > 0.0f))
            thB = fmaf(fB * 0.01f, rcp_approx(gB), thB);

        if (planes) {
            if (va) g_theta[(size_t)i * PLANE_ROWS + rowA] = thA;
            if (vb) g_theta[(size_t)i * PLANE_ROWS + rowB] = thB;
        }
    }

    __syncthreads();
    for (int idx = tid; idx < CAP1; idx += blockDim.x) {
        long long tot = 0;
#pragma unroll
        for (int w = 0; w < NW; ++w) tot += (long long)ss[w][idx];
        if (tot)
            atomicAdd(reinterpret_cast<unsigned long long*>(&g_sums[idx]),
                      (unsigned long long)tot);
    }

    __threadfence();
    __shared__ bool is_last;
    if (tid == 0)
        is_last = (atomicAdd(&g_done1, 1u) == (unsigned)(gridDim.x - 1));
    __syncthreads();
    if (is_last && tid == 0) {
        double denom = (double)nrows * FP_SCALE_D;
        int n = -1;   // -1 => continuation / fallback required
        for (int i = 0; i < CAP1; ++i) {
            double mean = (double)g_sums[i] / denom;
            if (mean < TOL) { n = i; break; }
        }
        g_nstar = n;
        __threadfence();
    }
}

// ---------------- continuation: iterations CAP1..CAP2-1 (cold) ----------------
__global__ void __launch_bounds__(256) k_cont(const float* __restrict__ s, int nrows) {
    if (g_nstar != -1) return;
    if (nrows > PLANE_ROWS) return;

    __shared__ int ss[NW][CAP2 - CAP1];
    const int tid  = threadIdx.x;
    const int wid  = tid >> 5;
    const int lane = tid & 31;

    if (tid < NW * (CAP2 - CAP1)) (&ss[0][0])[tid] = 0;
    __syncthreads();

    int row = blockIdx.x * blockDim.x + tid;
    bool valid = row < nrows;

    float t[S_DIM], b[S_DIM];
    float theta = 0.0f;
    if (valid) {
        load_row(s, row, t);
        theta = g_theta[(size_t)(CAP1 - 1) * PLANE_ROWS + row];  // exact resume
    } else {
#pragma unroll
        for (int j = 0; j < S_DIM; ++j) t[j] = 0.0f;
    }
#pragma unroll
    for (int j = 0; j < S_DIM; ++j) b[j] = t[j] * CEXP;

#pragma unroll 1
    for (int i = CAP1; i < CAP2; ++i) {
        float f, g;
        eval_fg_fast(b, theta, f, g);
        int fx = valid ? __float2int_rn(f * FP_SCALE) : 0;
        int wsum = __reduce_add_sync(0xffffffffu, fx);
        if (lane == 0) ss[wid][i - CAP1] = wsum;

        if (valid) {
            float thn = theta - __fdividef(f, -100.0f * g);
            if ((g > 0.0f) && (thn != theta)) theta = thn;
        }
        if (valid)
            g_theta[(size_t)i * PLANE_ROWS + row] = theta;
    }

    __syncthreads();
    for (int idx = tid; idx < CAP2 - CAP1; idx += blockDim.x) {
        long long tot = 0;
#pragma unroll
        for (int w = 0; w < NW; ++w) tot += (long long)ss[w][idx];
        if (tot)
            atomicAdd(reinterpret_cast<unsigned long long*>(&g_sums[CAP1 + idx]),
                      (unsigned long long)tot);
    }

    __threadfence();
    __shared__ bool is_last;
    if (tid == 0)
        is_last = (atomicAdd(&g_done_c, 1u) == (unsigned)(gridDim.x - 1));
    __syncthreads();
    if (is_last && tid == 0) {
        double denom = (double)nrows * FP_SCALE_D;
        int n = -1;
        for (int i = CAP1; i < CAP2; ++i) {
            double mean = (double)g_sums[i] / denom;
            if (mean < TOL) { n = i; break; }
        }
        g_nstar = n;    // stays -1 -> deep fallback
        __threadfence();
    }
}

// ---------------- deep fallback: exact full depth (cold) ----------------
__global__ void __launch_bounds__(256) k_fb_pass1(const float* __restrict__ s, int nrows) {
    if (g_nstar >= 0) return;

    __shared__ long long ss[NW][MAX_ITER];
    const int tid  = threadIdx.x;
    const int wid  = tid >> 5;
    const int lane = tid & 31;

    for (int i = tid; i < NW * MAX_ITER; i += blockDim.x)
        (&ss[0][0])[i] = 0;
    __syncthreads();

    const int stride = gridDim.x * blockDim.x;
    for (int row = blockIdx.x * blockDim.x + tid; ; row += stride) {
        bool valid = row < nrows;
        if (!__any_sync(0xffffffffu, valid)) break;

        float t[S_DIM];
        float theta = 0.0f;
        if (valid) {
            load_row(s, row, t);
            theta = third_largest(t);
        } else {
#pragma unroll
            for (int j = 0; j < S_DIM; ++j) t[j] = 0.0f;
        }

        bool frozen = !valid;
        int  i = 0;
        int  wsum = 0;

#pragma unroll 1
        for (; i < MAX_ITER; ++i) {
            float f, g;
            eval_fg(t, theta, f, g);
            int fx = valid ? __float2int_rn(f * FP_SCALE) : 0;
            wsum = __reduce_add_sync(0xffffffffu, fx);
            if (lane == 0) ss[wid][i] += (long long)wsum;

            if (!frozen) {
                float thn = theta - __fdividef(f, -100.0f * g);
                if ((g > 0.0f) && (thn != theta)) theta = thn;
                else frozen = true;
            }
            if (__all_sync(0xffffffffu, frozen)) { ++i; break; }
        }

        if (lane == 0 && i < MAX_ITER && wsum != 0)
            atomicAdd(reinterpret_cast<unsigned long long*>(&g_tail_fb[i]),
                      (unsigned long long)(long long)wsum);
    }

    __syncthreads();
    for (int idx = tid; idx < MAX_ITER; idx += blockDim.x) {
        long long tot = 0;
#pragma unroll
        for (int w = 0; w < NW; ++w) tot += ss[w][idx];
        if (tot)
            atomicAdd(reinterpret_cast<unsigned long long*>(&g_sums_fb[idx]),
                      (unsigned long long)tot);
    }

    __threadfence();
    __shared__ bool is_last;
    if (tid == 0)
        is_last = (atomicAdd(&g_done_fb, 1u) == (unsigned)(gridDim.x - 1));
    __syncthreads();
    if (is_last && tid == 0) {
        double denom = (double)nrows * FP_SCALE_D;
        long long carry = 0;
        int n = MAX_ITER;
        for (int i = 0; i < MAX_ITER; ++i) {
            carry += g_tail_fb[i];
            double mean = (double)(g_sums_fb[i] + carry) / denom;
            if (mean < TOL) { n = i; break; }
        }
        g_nstar = n;
        __threadfence();
    }
}

// ---------------- pass 2 ----------------
__global__ void __launch_bounds__(256) k_pass2(const float* __restrict__ s,
                                               float* __restrict__ out, int nrows) {
    int row = blockIdx.x * blockDim.x + threadIdx.x;
    if (row >= nrows) return;

    float t[S_DIM];
    load_row(s, row, t);

    int n = g_nstar;   // uniform across grid
    float theta;
    if (n > 0 && n <= CAP2 && nrows <= PLANE_ROWS) {
        theta = g_theta[(size_t)(n - 1) * PLANE_ROWS + row];   // theta after n updates
    } else if (n == 0) {
        theta = third_largest(t);
    } else {
        theta = third_largest(t);
#pragma unroll 1
        for (int i = 0; i < n; ++i) {
            float f, g;
            eval_fg(t, theta, f, g);
            float thn = theta - __fdividef(f, -100.0f * g);
            if ((g > 0.0f) && (thn != theta)) theta = thn;
            else break;
        }
    }

    float4 o0, o1;
    o0.x = sigmoid_f((t[0] - theta) * INV_TAU);
    o0.y = sigmoid_f((t[1] - theta) * INV_TAU);
    o0.z = sigmoid_f((t[2] - theta) * INV_TAU);
    o0.w = sigmoid_f((t[3] - theta) * INV_TAU);
    o1.x = sigmoid_f((t[4] - theta) * INV_TAU);
    o1.y = sigmoid_f((t[5] - theta) * INV_TAU);
    o1.z = sigmoid_f((t[6] - theta) * INV_TAU);
    o1.w = sigmoid_f((t[7] - theta) * INV_TAU);

    float4* po = reinterpret_cast<float4*>(out + (size_t)row * S_DIM);
    po[0] = o0;
    po[1] = o1;
}

extern "C" void kernel_launch(void* const* d_in, const int* in_sizes, int n_in,
                              void* d_out, int out_size) {
    const float* s = (const float*)d_in[0];
    float* out = (float*)d_out;
    int nrows = in_sizes[0] / S_DIM;

    k_zero<<<1, 128>>>();

    const int threads = 256;
    int blocks  = (nrows + threads - 1) / threads;
    int blocks2 = (nrows + 2 * threads - 1) / (2 * threads);   // 2 rows/thread
    k_pass1<<<blocks2, threads>>>(s, nrows);
    k_cont<<<blocks, threads>>>(s, nrows);      // cold unless n* >= CAP1
    k_fb_pass1<<<592, threads>>>(s, nrows);     // cold unless n* >= CAP2
    k_pass2<<<blocks, threads>>>(s, out, nrows);
}